// round 14
// baseline (speedup 1.0000x reference)
#include <cuda_runtime.h>
#include <cuda_bf16.h>
#include <math.h>
#include <stdint.h>

// Problem constants
#define XYDIM 16
#define ZDIM  16
#define SNUM  4096     // 16*16*16
#define VNUM  2048
#define BNUM  8
#define LNUM  32
#define WNUM  8

#define LOG5F 1.6094379124341003f

// ---------------- scratch (device globals: no allocation allowed) ----------------
__device__ float g_lse[SNUM];                      // row logsumexp of emis_w
__device__ float g_LQT[(size_t)VNUM * SNUM];       // smoothed log-emission, TRANSPOSED [v][s]  (32MB)
__device__ float g_allemis[LNUM * BNUM * SNUM];    // (L,B,S) emission sums + folded prior/amax
__device__ float g_P7[7 * SNUM];                   // exp(logp - amax), fixed-offset slots, [k][s]
__device__ float g_amax[SNUM];
__device__ float g_plse[1];                        // prior logsumexp

// warp-wide fp32 max via integer redux (sm_103a has no redux.f32).
// Order-preserving map fp32 -> s32: i>=0 ? i : i^0x7fffffff (handles ±inf).
__device__ __forceinline__ float redux_max_f32(float v) {
    int i = __float_as_int(v);
    i = (i >= 0) ? i : (i ^ 0x7fffffff);
    int r;
    asm volatile("redux.sync.max.s32 %0, %1, 0xffffffff;" : "=r"(r) : "r"(i));
    r = (r >= 0) ? r : (r ^ 0x7fffffff);
    return __int_as_float(r);
}

// ---------------- K_prep: fused row-lse (4096 blocks) + trans (16) + prior (1) ----------------
__global__ void k_prep(const float* __restrict__ emis,
                       const float* __restrict__ tw,
                       const float* __restrict__ pw) {
    int bid = blockIdx.x;
    int t = threadIdx.x;                 // 256 threads

    if (bid < SNUM) {
        int s = bid;
        const float4* row = reinterpret_cast<const float4*>(emis + (size_t)s * VNUM);
        float4 a = row[t];
        float4 b = row[t + 256];
        float mx = fmaxf(fmaxf(fmaxf(a.x, a.y), fmaxf(a.z, a.w)),
                         fmaxf(fmaxf(b.x, b.y), fmaxf(b.z, b.w)));
        __shared__ float red[8];
        #pragma unroll
        for (int o = 16; o; o >>= 1) mx = fmaxf(mx, __shfl_xor_sync(0xffffffffu, mx, o));
        if ((t & 31) == 0) red[t >> 5] = mx;
        __syncthreads();
        mx = red[0];
        #pragma unroll
        for (int k = 1; k < 8; k++) mx = fmaxf(mx, red[k]);
        float se = __expf(a.x - mx) + __expf(a.y - mx) + __expf(a.z - mx) + __expf(a.w - mx)
                 + __expf(b.x - mx) + __expf(b.y - mx) + __expf(b.z - mx) + __expf(b.w - mx);
        #pragma unroll
        for (int o = 16; o; o >>= 1) se += __shfl_xor_sync(0xffffffffu, se, o);
        __syncthreads();
        if ((t & 31) == 0) red[t >> 5] = se;
        __syncthreads();
        if (t == 0) {
            float sum = 0.f;
            #pragma unroll
            for (int k = 0; k < 8; k++) sum += red[k];
            g_lse[s] = mx + __logf(sum);
        }
    } else if (bid < SNUM + 16) {
        // transition log-softmax with stable valid-first pairing
        int j = (bid - SNUM) * 256 + t;
        int x = j & 15, y = (j >> 4) & 15, z = j >> 8;
        bool val[7] = { true, x < 15, x > 0, y < 15, y > 0, z < 15, z < 14 };
        float wv[7];
        int r = 0;
        float M = -INFINITY;
        #pragma unroll
        for (int i = 0; i < 7; i++) {
            if (val[i]) { wv[i] = tw[j * 7 + r]; r++; M = fmaxf(M, wv[i]); }
            else wv[i] = 0.f;
        }
        float sum = 0.f;
        #pragma unroll
        for (int i = 0; i < 7; i++) if (val[i]) sum += __expf(wv[i] - M);
        g_amax[j] = -__logf(sum);
        #pragma unroll
        for (int i = 0; i < 7; i++)
            g_P7[i * SNUM + j] = val[i] ? __expf(wv[i] - M) : 0.f;
    } else {
        // prior logsumexp
        float v[16];
        float mx = -INFINITY;
        #pragma unroll
        for (int k = 0; k < 16; k++) { v[k] = pw[t + 256 * k]; mx = fmaxf(mx, v[k]); }
        __shared__ float red2[8];
        #pragma unroll
        for (int o = 16; o; o >>= 1) mx = fmaxf(mx, __shfl_xor_sync(0xffffffffu, mx, o));
        if ((t & 31) == 0) red2[t >> 5] = mx;
        __syncthreads();
        mx = red2[0];
        #pragma unroll
        for (int k = 1; k < 8; k++) mx = fmaxf(mx, red2[k]);
        float se = 0.f;
        #pragma unroll
        for (int k = 0; k < 16; k++) se += __expf(v[k] - mx);
        #pragma unroll
        for (int o = 16; o; o >>= 1) se += __shfl_xor_sync(0xffffffffu, se, o);
        __syncthreads();
        if ((t & 31) == 0) red2[t >> 5] = se;
        __syncthreads();
        if (t == 0) {
            float sum = 0.f;
            #pragma unroll
            for (int k = 0; k < 8; k++) sum += red2[k];
            g_plse[0] = mx + __logf(sum);
        }
    }
}

// ---------------- K2: 5-point (y,x) smoothing -> transposed log table ----------------
__global__ void k_smooth(const float* __restrict__ emis) {
    __shared__ float sm[256][33];
    int v0 = blockIdx.x * 32;
    int z  = blockIdx.y;
    int t = threadIdx.x;
    int w = t >> 5, l = t & 31;
    int sbase = z * 256;
    #pragma unroll 4
    for (int rr = 0; rr < 32; rr++) {
        int r = w * 32 + rr;
        int s = sbase + r;
        float x = emis[(size_t)s * VNUM + v0 + l];
        sm[r][l] = __expf(x - g_lse[s]);
    }
    __syncthreads();
    int p = t;
    int x = p & 15, y = p >> 4;
    int pu = (y < 15) ? p + 16 : p;
    int pd = (y > 0)  ? p - 16 : p;
    int pl = (x < 15) ? p + 1  : p;
    int pr = (x > 0)  ? p - 1  : p;
    #pragma unroll 4
    for (int i = 0; i < 32; i++) {
        float Q = sm[p][i] + sm[pu][i] + sm[pd][i] + sm[pl][i] + sm[pr][i];
        g_LQT[(size_t)(v0 + i) * SNUM + sbase + p] = __logf(Q) - LOG5F;
    }
}

// ---------------- K3: token gather-sum -> all_emis, folding prior (l=0) / amax (l>0) ----------------
__global__ void k_gather(const int* __restrict__ stories, const float* __restrict__ pw) {
    int b = blockIdx.x, l = blockIdx.y;
    __shared__ int tok[WNUM];
    if (threadIdx.x < WNUM) tok[threadIdx.x] = stories[(b * LNUM + l) * WNUM + threadIdx.x];
    __syncthreads();
    int t = threadIdx.x;
    float plse = g_plse[0];
    float4* dst = reinterpret_cast<float4*>(g_allemis + ((size_t)l * BNUM + b) * SNUM);
    float4 acc[4];
    #pragma unroll
    for (int i = 0; i < 4; i++) {
        int j = (t + 256 * i) * 4;
        if (l == 0) {
            float4 q = *reinterpret_cast<const float4*>(&pw[j]);
            acc[i] = make_float4(q.x - plse, q.y - plse, q.z - plse, q.w - plse);
        } else {
            acc[i] = *reinterpret_cast<const float4*>(&g_amax[j]);
        }
    }
    #pragma unroll
    for (int w2 = 0; w2 < WNUM; w2++) {
        int tk = tok[w2];
        if (tk < VNUM) {
            const float4* row = reinterpret_cast<const float4*>(g_LQT + (size_t)tk * SNUM);
            #pragma unroll
            for (int i = 0; i < 4; i++) {
                float4 r = row[t + 256 * i];
                acc[i].x += r.x; acc[i].y += r.y; acc[i].z += r.z; acc[i].w += r.w;
            }
        }
    }
    #pragma unroll
    for (int i = 0; i < 4; i++) dst[t + 256 * i] = acc[i];
}

// ---------------- K5: forward recursion — ONE barrier/step, warp-factored scaling ----------------
// Each warp publishes p = exp(v - lm_w) (lm_w = warp max via redux, no barrier) plus
// lm_w in red[]. Consumers rebuild exp(v - M) = p * exp(lm_w' - M) with M = global
// max (redux over red[lane]); corrections <= 1, so underflow matches the reference.
// Warp map per offset: self/±1 -> own warp; ±16 -> own warp except 4 edge lanes
// (w-1 / w+1); +256 -> w+2; +512 -> w+4 (clamped indices only hit P7==0 halo terms).
// sp and red are double-buffered on step parity -> single __syncthreads covers
// both publication and WAR.
__global__ void __launch_bounds__(1024, 1)
k_forward(float* __restrict__ out) {
    __shared__ float sp[2][16 + SNUM + 512];   // [front16 | 4096 | back512] × 2
    __shared__ float red[2][32];
    int b = blockIdx.x;
    int t = threadIdx.x;                 // 1024 threads, 4 contiguous states each
    int wid = t >> 5, lane = t & 31;
    int j0 = t * 4;

    // persistent transition rows (coalesced float4 loads, [k][s] layout)
    float p7r[7][4];
    #pragma unroll
    for (int k = 0; k < 7; k++) {
        float4 a = *reinterpret_cast<const float4*>(&g_P7[k * SNUM + j0]);
        p7r[k][0] = a.x; p7r[k][1] = a.y; p7r[k][2] = a.z; p7r[k][3] = a.w;
    }

    // zero halos in BOTH buffers (never overwritten; P7==0 masks reads)
    if (t < 16)  { sp[0][t] = 0.f; sp[1][t] = 0.f; }
    if (t < 512) { sp[0][16 + SNUM + t] = 0.f; sp[1][16 + SNUM + t] = 0.f; }

    // l = 0: score0 fully materialized by k_gather (em + prior - plse)
    float v[4], p[4];
    {
        float4 e = *reinterpret_cast<const float4*>(&g_allemis[(size_t)b * SNUM + j0]);
        v[0] = e.x; v[1] = e.y; v[2] = e.z; v[3] = e.w;
        *reinterpret_cast<float4*>(&out[(size_t)b * SNUM + j0]) = e;
    }
    // tail of l=0 -> buffer 1
    float lm = redux_max_f32(fmaxf(fmaxf(v[0], v[1]), fmaxf(v[2], v[3])));
    lm = fmaxf(lm, -3.4e38f);
    #pragma unroll
    for (int st = 0; st < 4; st++) p[st] = __expf(v[st] - lm);
    *reinterpret_cast<float4*>(&sp[1][16 + j0]) = make_float4(p[0], p[1], p[2], p[3]);
    if (lane == 0) red[1][wid] = lm;
    float rgt = __shfl_down_sync(0xffffffffu, p[0], 1);  // +1 across thread edge
    float lft = __shfl_up_sync(0xffffffffu, p[3], 1);    // -1 across thread edge
    __syncthreads();

    int wm1 = (wid > 0)  ? wid - 1 : 0;
    int wp1 = (wid < 31) ? wid + 1 : 31;
    int wp2 = (wid < 30) ? wid + 2 : 31;
    int wp4 = (wid < 28) ? wid + 4 : 31;

    for (int l = 1; l < LNUM; l++) {
        int bi = l & 1;
        // emissions (independent load, issued early)
        float4 emv = *reinterpret_cast<const float4*>(
            g_allemis + ((size_t)l * BNUM + b) * SNUM + j0);
        // global max + per-warp corrections (all <= 1)
        float M  = redux_max_f32(red[bi][lane]);
        float cs  = __expf(lm - M);
        float cm1 = __expf(red[bi][wm1] - M);
        float cp1 = __expf(red[bi][wp1] - M);
        float c2  = __expf(red[bi][wp2] - M);
        float c4  = __expf(red[bi][wp4] - M);
        float corrm = (lane <  4) ? cm1 : cs;   // -16 crosses into warp w-1 for lanes 0..3
        float corrp = (lane >= 28) ? cp1 : cs;  // +16 crosses into warp w+1 for lanes 28..31

        const float* S = sp[bi];
        float4 u16  = *reinterpret_cast<const float4*>(&S[16 + j0 + 16]);
        float4 d16  = *reinterpret_cast<const float4*>(&S[16 + j0 - 16]);
        float4 u256 = *reinterpret_cast<const float4*>(&S[16 + j0 + 256]);
        float4 u512 = *reinterpret_cast<const float4*>(&S[16 + j0 + 512]);
        float n16[4]  = { u16.x, u16.y, u16.z, u16.w };
        float m16[4]  = { d16.x, d16.y, d16.z, d16.w };
        float n256[4] = { u256.x, u256.y, u256.z, u256.w };
        float n512[4] = { u512.x, u512.y, u512.z, u512.w };
        float em[4]   = { emv.x, emv.y, emv.z, emv.w };

        #pragma unroll
        for (int st = 0; st < 4; st++) {
            float rn = (st < 3) ? p[st + 1] : rgt;
            float ln = (st > 0) ? p[st - 1] : lft;
            float acc = cs * (p7r[0][st] * p[st] + p7r[1][st] * rn + p7r[2][st] * ln)
                      + corrp * (p7r[3][st] * n16[st])
                      + corrm * (p7r[4][st] * m16[st])
                      + c2    * (p7r[5][st] * n256[st])
                      + c4    * (p7r[6][st] * n512[st]);
            v[st] = em[st] + __logf(acc) + M;   // amax folded into em
        }

        // tail: publish next buffers
        float lmn = redux_max_f32(fmaxf(fmaxf(v[0], v[1]), fmaxf(v[2], v[3])));
        lmn = fmaxf(lmn, -3.4e38f);
        #pragma unroll
        for (int st = 0; st < 4; st++) p[st] = __expf(v[st] - lmn);
        *reinterpret_cast<float4*>(&sp[bi ^ 1][16 + j0]) = make_float4(p[0], p[1], p[2], p[3]);
        if (lane == 0) red[bi ^ 1][wid] = lmn;
        rgt = __shfl_down_sync(0xffffffffu, p[0], 1);
        lft = __shfl_up_sync(0xffffffffu, p[3], 1);
        *reinterpret_cast<float4*>(out + ((size_t)l * BNUM + b) * SNUM + j0)
            = make_float4(v[0], v[1], v[2], v[3]);
        lm = lmn;
        __syncthreads();
    }
}

// ---------------- launch ----------------
extern "C" void kernel_launch(void* const* d_in, const int* in_sizes, int n_in,
                              void* d_out, int out_size) {
    const int*   stories = nullptr;
    const float* trans_w = nullptr;
    const float* emis_w  = nullptr;
    const float* prior_w = nullptr;
    for (int i = 0; i < n_in; i++) {
        switch (in_sizes[i]) {
            case BNUM * LNUM * WNUM: stories = (const int*)d_in[i];   break; // 2048
            case SNUM * 7:           trans_w = (const float*)d_in[i]; break; // 28672
            case SNUM * VNUM:        emis_w  = (const float*)d_in[i]; break; // 8388608
            case SNUM:               prior_w = (const float*)d_in[i]; break; // 4096
            default: break; // story_length scalar
        }
    }
    float* out = (float*)d_out;

    k_prep<<<SNUM + 16 + 1, 256>>>(emis_w, trans_w, prior_w);
    k_smooth<<<dim3(VNUM / 32, ZDIM), 256>>>(emis_w);
    k_gather<<<dim3(BNUM, LNUM), 256>>>(stories, prior_w);
    k_forward<<<BNUM, 1024>>>(out);
}

// round 15
// speedup vs baseline: 1.0319x; 1.0319x over previous
#include <cuda_runtime.h>
#include <cuda_bf16.h>
#include <math.h>
#include <stdint.h>

// Problem constants
#define XYDIM 16
#define ZDIM  16
#define SNUM  4096     // 16*16*16
#define VNUM  2048
#define BNUM  8
#define LNUM  32
#define WNUM  8

#define LOG5F 1.6094379124341003f

// ---------------- scratch (device globals: no allocation allowed) ----------------
__device__ float g_lse[SNUM];                      // row logsumexp of emis_w
__device__ float g_LQT[(size_t)VNUM * SNUM];       // smoothed log-emission, TRANSPOSED [v][s]  (32MB)
__device__ float g_allemis[LNUM * BNUM * SNUM];    // (L,B,S) emission sums + folded prior/amax
__device__ float g_P7[7 * SNUM];                   // exp(logp - amax), fixed-offset slots, [k][s]
__device__ float g_amax[SNUM];
__device__ float g_plse[1];                        // prior logsumexp

// warp-wide fp32 max via integer redux (sm_103a has no redux.f32).
// Order-preserving map fp32 -> s32: i>=0 ? i : i^0x7fffffff (handles ±inf).
__device__ __forceinline__ float redux_max_f32(float v) {
    int i = __float_as_int(v);
    i = (i >= 0) ? i : (i ^ 0x7fffffff);
    int r;
    asm volatile("redux.sync.max.s32 %0, %1, 0xffffffff;" : "=r"(r) : "r"(i));
    r = (r >= 0) ? r : (r ^ 0x7fffffff);
    return __int_as_float(r);
}

// ---------------- K_prep: fused row-lse (4096 blocks) + trans (16) + prior (1) ----------------
__global__ void k_prep(const float* __restrict__ emis,
                       const float* __restrict__ tw,
                       const float* __restrict__ pw) {
    int bid = blockIdx.x;
    int t = threadIdx.x;                 // 256 threads

    if (bid < SNUM) {
        int s = bid;
        const float4* row = reinterpret_cast<const float4*>(emis + (size_t)s * VNUM);
        float4 a = row[t];
        float4 b = row[t + 256];
        float mx = fmaxf(fmaxf(fmaxf(a.x, a.y), fmaxf(a.z, a.w)),
                         fmaxf(fmaxf(b.x, b.y), fmaxf(b.z, b.w)));
        __shared__ float red[8];
        #pragma unroll
        for (int o = 16; o; o >>= 1) mx = fmaxf(mx, __shfl_xor_sync(0xffffffffu, mx, o));
        if ((t & 31) == 0) red[t >> 5] = mx;
        __syncthreads();
        mx = red[0];
        #pragma unroll
        for (int k = 1; k < 8; k++) mx = fmaxf(mx, red[k]);
        float se = __expf(a.x - mx) + __expf(a.y - mx) + __expf(a.z - mx) + __expf(a.w - mx)
                 + __expf(b.x - mx) + __expf(b.y - mx) + __expf(b.z - mx) + __expf(b.w - mx);
        #pragma unroll
        for (int o = 16; o; o >>= 1) se += __shfl_xor_sync(0xffffffffu, se, o);
        __syncthreads();
        if ((t & 31) == 0) red[t >> 5] = se;
        __syncthreads();
        if (t == 0) {
            float sum = 0.f;
            #pragma unroll
            for (int k = 0; k < 8; k++) sum += red[k];
            g_lse[s] = mx + __logf(sum);
        }
    } else if (bid < SNUM + 16) {
        // transition log-softmax with stable valid-first pairing
        int j = (bid - SNUM) * 256 + t;
        int x = j & 15, y = (j >> 4) & 15, z = j >> 8;
        bool val[7] = { true, x < 15, x > 0, y < 15, y > 0, z < 15, z < 14 };
        float wv[7];
        int r = 0;
        float M = -INFINITY;
        #pragma unroll
        for (int i = 0; i < 7; i++) {
            if (val[i]) { wv[i] = tw[j * 7 + r]; r++; M = fmaxf(M, wv[i]); }
            else wv[i] = 0.f;
        }
        float sum = 0.f;
        #pragma unroll
        for (int i = 0; i < 7; i++) if (val[i]) sum += __expf(wv[i] - M);
        g_amax[j] = -__logf(sum);
        #pragma unroll
        for (int i = 0; i < 7; i++)
            g_P7[i * SNUM + j] = val[i] ? __expf(wv[i] - M) : 0.f;
    } else {
        // prior logsumexp
        float v[16];
        float mx = -INFINITY;
        #pragma unroll
        for (int k = 0; k < 16; k++) { v[k] = pw[t + 256 * k]; mx = fmaxf(mx, v[k]); }
        __shared__ float red2[8];
        #pragma unroll
        for (int o = 16; o; o >>= 1) mx = fmaxf(mx, __shfl_xor_sync(0xffffffffu, mx, o));
        if ((t & 31) == 0) red2[t >> 5] = mx;
        __syncthreads();
        mx = red2[0];
        #pragma unroll
        for (int k = 1; k < 8; k++) mx = fmaxf(mx, red2[k]);
        float se = 0.f;
        #pragma unroll
        for (int k = 0; k < 16; k++) se += __expf(v[k] - mx);
        #pragma unroll
        for (int o = 16; o; o >>= 1) se += __shfl_xor_sync(0xffffffffu, se, o);
        __syncthreads();
        if ((t & 31) == 0) red2[t >> 5] = se;
        __syncthreads();
        if (t == 0) {
            float sum = 0.f;
            #pragma unroll
            for (int k = 0; k < 8; k++) sum += red2[k];
            g_plse[0] = mx + __logf(sum);
        }
    }
}

// ---------------- K2: 5-point (y,x) smoothing -> transposed log table ----------------
__global__ void k_smooth(const float* __restrict__ emis) {
    __shared__ float sm[256][33];
    int v0 = blockIdx.x * 32;
    int z  = blockIdx.y;
    int t = threadIdx.x;
    int w = t >> 5, l = t & 31;
    int sbase = z * 256;
    #pragma unroll 4
    for (int rr = 0; rr < 32; rr++) {
        int r = w * 32 + rr;
        int s = sbase + r;
        float x = emis[(size_t)s * VNUM + v0 + l];
        sm[r][l] = __expf(x - g_lse[s]);
    }
    __syncthreads();
    int p = t;
    int x = p & 15, y = p >> 4;
    int pu = (y < 15) ? p + 16 : p;
    int pd = (y > 0)  ? p - 16 : p;
    int pl = (x < 15) ? p + 1  : p;
    int pr = (x > 0)  ? p - 1  : p;
    #pragma unroll 4
    for (int i = 0; i < 32; i++) {
        float Q = sm[p][i] + sm[pu][i] + sm[pd][i] + sm[pl][i] + sm[pr][i];
        g_LQT[(size_t)(v0 + i) * SNUM + sbase + p] = __logf(Q) - LOG5F;
    }
}

// ---------------- K3: token gather-sum -> all_emis, folding prior (l=0) / amax (l>0) ----------------
__global__ void k_gather(const int* __restrict__ stories, const float* __restrict__ pw) {
    int b = blockIdx.x, l = blockIdx.y;
    __shared__ int tok[WNUM];
    if (threadIdx.x < WNUM) tok[threadIdx.x] = stories[(b * LNUM + l) * WNUM + threadIdx.x];
    __syncthreads();
    int t = threadIdx.x;
    float plse = g_plse[0];
    float4* dst = reinterpret_cast<float4*>(g_allemis + ((size_t)l * BNUM + b) * SNUM);
    float4 acc[4];
    #pragma unroll
    for (int i = 0; i < 4; i++) {
        int j = (t + 256 * i) * 4;
        if (l == 0) {
            float4 q = *reinterpret_cast<const float4*>(&pw[j]);
            acc[i] = make_float4(q.x - plse, q.y - plse, q.z - plse, q.w - plse);
        } else {
            acc[i] = *reinterpret_cast<const float4*>(&g_amax[j]);
        }
    }
    #pragma unroll
    for (int w2 = 0; w2 < WNUM; w2++) {
        int tk = tok[w2];
        if (tk < VNUM) {
            const float4* row = reinterpret_cast<const float4*>(g_LQT + (size_t)tk * SNUM);
            #pragma unroll
            for (int i = 0; i < 4; i++) {
                float4 r = row[t + 256 * i];
                acc[i].x += r.x; acc[i].y += r.y; acc[i].z += r.z; acc[i].w += r.w;
            }
        }
    }
    #pragma unroll
    for (int i = 0; i < 4; i++) dst[t + 256 * i] = acc[i];
}

// ---------------- K5: forward recursion — ONE barrier/step, LOCAL-max scaling ----------------
// Each warp publishes p = exp(v - lm_w) (lm_w = warp max via redux, tail) + lm_w in red[].
// Consumers pick m = max over the <=4 warp maxima actually feeding their stencil
// (own, y-edge warp, w+2 for +256, w+4 for +512) -> all corrections <= 1, no overflow,
// underflow no worse than the reference's global max. m cancels algebraically, so any
// per-state-consistent m is exact; no global redux, no second barrier.
// Warp w owns 128 contiguous states = an 8-row y-slab: EVEN warps only cross +16 (to
// w+1, lanes 28-31; their y=0 side is a true face, P7==0); ODD warps only cross -16
// (to w-1, lanes 0-3; y=15 side is a face). +256 -> w+2, +512 -> w+4 (clamped indices
// only ever scale P7==0 halo terms). sp/red double-buffered on step parity.
__global__ void __launch_bounds__(1024, 1)
k_forward(float* __restrict__ out) {
    __shared__ float sp[2][16 + SNUM + 512];   // [front16 | 4096 | back512] × 2
    __shared__ float red[2][32];
    int b = blockIdx.x;
    int t = threadIdx.x;                 // 1024 threads, 4 contiguous states each
    int wid = t >> 5, lane = t & 31;
    int j0 = t * 4;
    bool oddw = (wid & 1) != 0;
    int wEdge = oddw ? wid - 1 : wid + 1;          // the one y-crossing partner
    int wp2 = (wid < 30) ? wid + 2 : 31;           // +256 source warp (clamp -> halo-only)
    int wp4 = (wid < 28) ? wid + 4 : 31;           // +512 source warp (clamp -> halo-only)

    // persistent transition rows (coalesced float4 loads, [k][s] layout)
    float p7r[7][4];
    #pragma unroll
    for (int k = 0; k < 7; k++) {
        float4 a = *reinterpret_cast<const float4*>(&g_P7[k * SNUM + j0]);
        p7r[k][0] = a.x; p7r[k][1] = a.y; p7r[k][2] = a.z; p7r[k][3] = a.w;
    }

    // zero halos in BOTH buffers (never overwritten; P7==0 masks reads)
    if (t < 16)  { sp[0][t] = 0.f; sp[1][t] = 0.f; }
    if (t < 512) { sp[0][16 + SNUM + t] = 0.f; sp[1][16 + SNUM + t] = 0.f; }

    // l = 0: score0 fully materialized by k_gather (em + prior - plse)
    float v[4], p[4];
    {
        float4 e = *reinterpret_cast<const float4*>(&g_allemis[(size_t)b * SNUM + j0]);
        v[0] = e.x; v[1] = e.y; v[2] = e.z; v[3] = e.w;
        *reinterpret_cast<float4*>(&out[(size_t)b * SNUM + j0]) = e;
    }
    // tail of l=0 -> buffer 1
    float lm = redux_max_f32(fmaxf(fmaxf(v[0], v[1]), fmaxf(v[2], v[3])));
    lm = fmaxf(lm, -3.4e38f);
    #pragma unroll
    for (int st = 0; st < 4; st++) p[st] = __expf(v[st] - lm);
    *reinterpret_cast<float4*>(&sp[1][16 + j0]) = make_float4(p[0], p[1], p[2], p[3]);
    if (lane == 0) red[1][wid] = lm;
    float rgt = __shfl_down_sync(0xffffffffu, p[0], 1);  // +1 across thread edge
    float lft = __shfl_up_sync(0xffffffffu, p[3], 1);    // -1 across thread edge
    __syncthreads();

    for (int l = 1; l < LNUM; l++) {
        int bi = l & 1;
        // emissions (independent load, issued early)
        float4 emv = *reinterpret_cast<const float4*>(
            g_allemis + ((size_t)l * BNUM + b) * SNUM + j0);
        // local neighborhood max + corrections (all <= 1)
        float rE = red[bi][wEdge];
        float r2 = red[bi][wp2];
        float r4 = red[bi][wp4];
        float m = fmaxf(fmaxf(fmaxf(lm, rE), fmaxf(r2, r4)), -3.4e38f);
        float cs = __expf(lm - m);
        float cE = __expf(rE - m);
        float c2 = __expf(r2 - m);
        float c4 = __expf(r4 - m);
        float corrm = (oddw  && lane <  4) ? cE : cs;   // -16 crosses only from odd warps
        float corrp = (!oddw && lane >= 28) ? cE : cs;  // +16 crosses only from even warps

        const float* S = sp[bi];
        float4 u16  = *reinterpret_cast<const float4*>(&S[16 + j0 + 16]);
        float4 d16  = *reinterpret_cast<const float4*>(&S[16 + j0 - 16]);
        float4 u256 = *reinterpret_cast<const float4*>(&S[16 + j0 + 256]);
        float4 u512 = *reinterpret_cast<const float4*>(&S[16 + j0 + 512]);
        float n16[4]  = { u16.x, u16.y, u16.z, u16.w };
        float m16[4]  = { d16.x, d16.y, d16.z, d16.w };
        float n256[4] = { u256.x, u256.y, u256.z, u256.w };
        float n512[4] = { u512.x, u512.y, u512.z, u512.w };
        float em[4]   = { emv.x, emv.y, emv.z, emv.w };

        #pragma unroll
        for (int st = 0; st < 4; st++) {
            float rn = (st < 3) ? p[st + 1] : rgt;
            float ln = (st > 0) ? p[st - 1] : lft;
            float acc = cs * (p7r[0][st] * p[st] + p7r[1][st] * rn + p7r[2][st] * ln)
                      + corrp * (p7r[3][st] * n16[st])
                      + corrm * (p7r[4][st] * m16[st])
                      + c2    * (p7r[5][st] * n256[st])
                      + c4    * (p7r[6][st] * n512[st]);
            v[st] = em[st] + __logf(acc) + m;   // amax folded into em
        }

        // tail: publish next buffers
        float lmn = redux_max_f32(fmaxf(fmaxf(v[0], v[1]), fmaxf(v[2], v[3])));
        lmn = fmaxf(lmn, -3.4e38f);
        #pragma unroll
        for (int st = 0; st < 4; st++) p[st] = __expf(v[st] - lmn);
        *reinterpret_cast<float4*>(&sp[bi ^ 1][16 + j0]) = make_float4(p[0], p[1], p[2], p[3]);
        if (lane == 0) red[bi ^ 1][wid] = lmn;
        rgt = __shfl_down_sync(0xffffffffu, p[0], 1);
        lft = __shfl_up_sync(0xffffffffu, p[3], 1);
        *reinterpret_cast<float4*>(out + ((size_t)l * BNUM + b) * SNUM + j0)
            = make_float4(v[0], v[1], v[2], v[3]);
        lm = lmn;
        __syncthreads();
    }
}

// ---------------- launch ----------------
extern "C" void kernel_launch(void* const* d_in, const int* in_sizes, int n_in,
                              void* d_out, int out_size) {
    const int*   stories = nullptr;
    const float* trans_w = nullptr;
    const float* emis_w  = nullptr;
    const float* prior_w = nullptr;
    for (int i = 0; i < n_in; i++) {
        switch (in_sizes[i]) {
            case BNUM * LNUM * WNUM: stories = (const int*)d_in[i];   break; // 2048
            case SNUM * 7:           trans_w = (const float*)d_in[i]; break; // 28672
            case SNUM * VNUM:        emis_w  = (const float*)d_in[i]; break; // 8388608
            case SNUM:               prior_w = (const float*)d_in[i]; break; // 4096
            default: break; // story_length scalar
        }
    }
    float* out = (float*)d_out;

    k_prep<<<SNUM + 16 + 1, 256>>>(emis_w, trans_w, prior_w);
    k_smooth<<<dim3(VNUM / 32, ZDIM), 256>>>(emis_w);
    k_gather<<<dim3(BNUM, LNUM), 256>>>(stories, prior_w);
    k_forward<<<BNUM, 1024>>>(out);
}

// round 16
// speedup vs baseline: 1.1455x; 1.1101x over previous
#include <cuda_runtime.h>
#include <cuda_bf16.h>
#include <math.h>
#include <stdint.h>

// Problem constants
#define XYDIM 16
#define ZDIM  16
#define SNUM  4096     // 16*16*16
#define VNUM  2048
#define BNUM  8
#define LNUM  32
#define WNUM  8

#define LOG5F 1.6094379124341003f

// ---------------- scratch (device globals: no allocation allowed) ----------------
__device__ float g_lse[SNUM];                      // row logsumexp of emis_w
__device__ float g_LQT[(size_t)VNUM * SNUM];       // smoothed log-emission, TRANSPOSED [v][s]  (32MB)
__device__ float g_allemis[LNUM * BNUM * SNUM];    // (L,B,S) emission sums + folded prior/amax
__device__ float g_P7[7 * SNUM];                   // exp(logp - amax), fixed-offset slots, [k][s]
__device__ float g_amax[SNUM];
__device__ float g_plse[1];                        // prior logsumexp

// warp-wide fp32 max via integer redux (sm_103a has no redux.f32).
// Order-preserving map fp32 -> s32: i>=0 ? i : i^0x7fffffff (handles ±inf).
__device__ __forceinline__ float redux_max_f32(float v) {
    int i = __float_as_int(v);
    i = (i >= 0) ? i : (i ^ 0x7fffffff);
    int r;
    asm volatile("redux.sync.max.s32 %0, %1, 0xffffffff;" : "=r"(r) : "r"(i));
    r = (r >= 0) ? r : (r ^ 0x7fffffff);
    return __int_as_float(r);
}

// ---- packed f32x2 helpers (FFMA2/FMUL2 — PTX-only, same rounding as scalar) ----
typedef unsigned long long ull;
__device__ __forceinline__ ull f2_pack(float lo, float hi) {
    ull r; asm("mov.b64 %0, {%1, %2};" : "=l"(r) : "f"(lo), "f"(hi)); return r;
}
__device__ __forceinline__ void f2_unpack(float& lo, float& hi, ull v) {
    asm("mov.b64 {%0, %1}, %2;" : "=f"(lo), "=f"(hi) : "l"(v));
}
__device__ __forceinline__ ull f2_mul(ull a, ull b) {
    ull r; asm("mul.rn.f32x2 %0, %1, %2;" : "=l"(r) : "l"(a), "l"(b)); return r;
}
__device__ __forceinline__ ull f2_fma(ull a, ull b, ull c) {
    ull r; asm("fma.rn.f32x2 %0, %1, %2, %3;" : "=l"(r) : "l"(a), "l"(b), "l"(c)); return r;
}

// ---------------- K_prep: fused row-lse (4096 blocks) + trans (16) + prior (1) ----------------
__global__ void k_prep(const float* __restrict__ emis,
                       const float* __restrict__ tw,
                       const float* __restrict__ pw) {
    int bid = blockIdx.x;
    int t = threadIdx.x;                 // 256 threads

    if (bid < SNUM) {
        int s = bid;
        const float4* row = reinterpret_cast<const float4*>(emis + (size_t)s * VNUM);
        float4 a = row[t];
        float4 b = row[t + 256];
        float mx = fmaxf(fmaxf(fmaxf(a.x, a.y), fmaxf(a.z, a.w)),
                         fmaxf(fmaxf(b.x, b.y), fmaxf(b.z, b.w)));
        __shared__ float red[8];
        #pragma unroll
        for (int o = 16; o; o >>= 1) mx = fmaxf(mx, __shfl_xor_sync(0xffffffffu, mx, o));
        if ((t & 31) == 0) red[t >> 5] = mx;
        __syncthreads();
        mx = red[0];
        #pragma unroll
        for (int k = 1; k < 8; k++) mx = fmaxf(mx, red[k]);
        float se = __expf(a.x - mx) + __expf(a.y - mx) + __expf(a.z - mx) + __expf(a.w - mx)
                 + __expf(b.x - mx) + __expf(b.y - mx) + __expf(b.z - mx) + __expf(b.w - mx);
        #pragma unroll
        for (int o = 16; o; o >>= 1) se += __shfl_xor_sync(0xffffffffu, se, o);
        __syncthreads();
        if ((t & 31) == 0) red[t >> 5] = se;
        __syncthreads();
        if (t == 0) {
            float sum = 0.f;
            #pragma unroll
            for (int k = 0; k < 8; k++) sum += red[k];
            g_lse[s] = mx + __logf(sum);
        }
    } else if (bid < SNUM + 16) {
        // transition log-softmax with stable valid-first pairing
        int j = (bid - SNUM) * 256 + t;
        int x = j & 15, y = (j >> 4) & 15, z = j >> 8;
        bool val[7] = { true, x < 15, x > 0, y < 15, y > 0, z < 15, z < 14 };
        float wv[7];
        int r = 0;
        float M = -INFINITY;
        #pragma unroll
        for (int i = 0; i < 7; i++) {
            if (val[i]) { wv[i] = tw[j * 7 + r]; r++; M = fmaxf(M, wv[i]); }
            else wv[i] = 0.f;
        }
        float sum = 0.f;
        #pragma unroll
        for (int i = 0; i < 7; i++) if (val[i]) sum += __expf(wv[i] - M);
        g_amax[j] = -__logf(sum);
        #pragma unroll
        for (int i = 0; i < 7; i++)
            g_P7[i * SNUM + j] = val[i] ? __expf(wv[i] - M) : 0.f;
    } else {
        // prior logsumexp
        float v[16];
        float mx = -INFINITY;
        #pragma unroll
        for (int k = 0; k < 16; k++) { v[k] = pw[t + 256 * k]; mx = fmaxf(mx, v[k]); }
        __shared__ float red2[8];
        #pragma unroll
        for (int o = 16; o; o >>= 1) mx = fmaxf(mx, __shfl_xor_sync(0xffffffffu, mx, o));
        if ((t & 31) == 0) red2[t >> 5] = mx;
        __syncthreads();
        mx = red2[0];
        #pragma unroll
        for (int k = 1; k < 8; k++) mx = fmaxf(mx, red2[k]);
        float se = 0.f;
        #pragma unroll
        for (int k = 0; k < 16; k++) se += __expf(v[k] - mx);
        #pragma unroll
        for (int o = 16; o; o >>= 1) se += __shfl_xor_sync(0xffffffffu, se, o);
        __syncthreads();
        if ((t & 31) == 0) red2[t >> 5] = se;
        __syncthreads();
        if (t == 0) {
            float sum = 0.f;
            #pragma unroll
            for (int k = 0; k < 8; k++) sum += red2[k];
            g_plse[0] = mx + __logf(sum);
        }
    }
}

// ---------------- K2: 5-point (y,x) smoothing -> transposed log table ----------------
__global__ void k_smooth(const float* __restrict__ emis) {
    __shared__ float sm[256][33];
    int v0 = blockIdx.x * 32;
    int z  = blockIdx.y;
    int t = threadIdx.x;
    int w = t >> 5, l = t & 31;
    int sbase = z * 256;
    #pragma unroll 4
    for (int rr = 0; rr < 32; rr++) {
        int r = w * 32 + rr;
        int s = sbase + r;
        float x = emis[(size_t)s * VNUM + v0 + l];
        sm[r][l] = __expf(x - g_lse[s]);
    }
    __syncthreads();
    int p = t;
    int x = p & 15, y = p >> 4;
    int pu = (y < 15) ? p + 16 : p;
    int pd = (y > 0)  ? p - 16 : p;
    int pl = (x < 15) ? p + 1  : p;
    int pr = (x > 0)  ? p - 1  : p;
    #pragma unroll 4
    for (int i = 0; i < 32; i++) {
        float Q = sm[p][i] + sm[pu][i] + sm[pd][i] + sm[pl][i] + sm[pr][i];
        g_LQT[(size_t)(v0 + i) * SNUM + sbase + p] = __logf(Q) - LOG5F;
    }
}

// ---------------- K3: token gather-sum -> all_emis, folding prior (l=0) / amax (l>0) ----------------
__global__ void k_gather(const int* __restrict__ stories, const float* __restrict__ pw) {
    int b = blockIdx.x, l = blockIdx.y;
    __shared__ int tok[WNUM];
    if (threadIdx.x < WNUM) tok[threadIdx.x] = stories[(b * LNUM + l) * WNUM + threadIdx.x];
    __syncthreads();
    int t = threadIdx.x;
    float plse = g_plse[0];
    float4* dst = reinterpret_cast<float4*>(g_allemis + ((size_t)l * BNUM + b) * SNUM);
    float4 acc[4];
    #pragma unroll
    for (int i = 0; i < 4; i++) {
        int j = (t + 256 * i) * 4;
        if (l == 0) {
            float4 q = *reinterpret_cast<const float4*>(&pw[j]);
            acc[i] = make_float4(q.x - plse, q.y - plse, q.z - plse, q.w - plse);
        } else {
            acc[i] = *reinterpret_cast<const float4*>(&g_amax[j]);
        }
    }
    #pragma unroll
    for (int w2 = 0; w2 < WNUM; w2++) {
        int tk = tok[w2];
        if (tk < VNUM) {
            const float4* row = reinterpret_cast<const float4*>(g_LQT + (size_t)tk * SNUM);
            #pragma unroll
            for (int i = 0; i < 4; i++) {
                float4 r = row[t + 256 * i];
                acc[i].x += r.x; acc[i].y += r.y; acc[i].z += r.z; acc[i].w += r.w;
            }
        }
    }
    #pragma unroll
    for (int i = 0; i < 4; i++) dst[t + 256 * i] = acc[i];
}

// ---------------- K5: forward recursion — ONE barrier/step, LOCAL-max scaling, FFMA2 stencil ----------------
// As R15 (warp-local scaling, single barrier, double-buffered sp/red) with:
//  * the 4-state stencil computed as 2 packed f32x2 chains (FFMA2: identical rounding,
//    half the FMA instruction stream),
//  * next-step emission prefetched at the step tail (hides the L2 hit).
__global__ void __launch_bounds__(1024, 1)
k_forward(float* __restrict__ out) {
    __shared__ float sp[2][16 + SNUM + 512];   // [front16 | 4096 | back512] × 2
    __shared__ float red[2][32];
    int b = blockIdx.x;
    int t = threadIdx.x;                 // 1024 threads, 4 contiguous states each
    int wid = t >> 5, lane = t & 31;
    int j0 = t * 4;
    bool oddw = (wid & 1) != 0;
    int wEdge = oddw ? wid - 1 : wid + 1;          // the one y-crossing partner
    int wp2 = (wid < 30) ? wid + 2 : 31;           // +256 source warp (clamp -> halo-only)
    int wp4 = (wid < 28) ? wid + 4 : 31;           // +512 source warp (clamp -> halo-only)

    // persistent transition rows, packed into f32x2 pairs ([k][s] layout loads)
    ull c01[7], c23[7];
    #pragma unroll
    for (int k = 0; k < 7; k++) {
        float4 a = *reinterpret_cast<const float4*>(&g_P7[k * SNUM + j0]);
        c01[k] = f2_pack(a.x, a.y);
        c23[k] = f2_pack(a.z, a.w);
    }

    // zero halos in BOTH buffers (never overwritten; P7==0 masks reads)
    if (t < 16)  { sp[0][t] = 0.f; sp[1][t] = 0.f; }
    if (t < 512) { sp[0][16 + SNUM + t] = 0.f; sp[1][16 + SNUM + t] = 0.f; }

    // l = 0: score0 fully materialized by k_gather (em + prior - plse)
    float v[4], p[4];
    {
        float4 e = *reinterpret_cast<const float4*>(&g_allemis[(size_t)b * SNUM + j0]);
        v[0] = e.x; v[1] = e.y; v[2] = e.z; v[3] = e.w;
        *reinterpret_cast<float4*>(&out[(size_t)b * SNUM + j0]) = e;
    }
    // tail of l=0 -> buffer 1
    float lm = redux_max_f32(fmaxf(fmaxf(v[0], v[1]), fmaxf(v[2], v[3])));
    lm = fmaxf(lm, -3.4e38f);
    #pragma unroll
    for (int st = 0; st < 4; st++) p[st] = __expf(v[st] - lm);
    *reinterpret_cast<float4*>(&sp[1][16 + j0]) = make_float4(p[0], p[1], p[2], p[3]);
    if (lane == 0) red[1][wid] = lm;
    float rgt = __shfl_down_sync(0xffffffffu, p[0], 1);  // +1 across thread edge
    float lft = __shfl_up_sync(0xffffffffu, p[3], 1);    // -1 across thread edge
    // prefetch emissions for l = 1
    float4 emv = *reinterpret_cast<const float4*>(
        g_allemis + ((size_t)1 * BNUM + b) * SNUM + j0);
    __syncthreads();

    for (int l = 1; l < LNUM; l++) {
        int bi = l & 1;
        // local neighborhood max + corrections (all <= 1)
        float rE = red[bi][wEdge];
        float r2 = red[bi][wp2];
        float r4 = red[bi][wp4];
        float m = fmaxf(fmaxf(fmaxf(lm, rE), fmaxf(r2, r4)), -3.4e38f);
        float cs = __expf(lm - m);
        float cE = __expf(rE - m);
        float c2 = __expf(r2 - m);
        float c4 = __expf(r4 - m);
        float corrm = (oddw  && lane <  4) ? cE : cs;   // -16 crosses only from odd warps
        float corrp = (!oddw && lane >= 28) ? cE : cs;  // +16 crosses only from even warps
        ull csP = f2_pack(cs, cs);
        ull cpP = f2_pack(corrp, corrp);
        ull cmP = f2_pack(corrm, corrm);
        ull c2P = f2_pack(c2, c2);
        ull c4P = f2_pack(c4, c4);

        const float* S = sp[bi];
        float4 u16  = *reinterpret_cast<const float4*>(&S[16 + j0 + 16]);
        float4 d16  = *reinterpret_cast<const float4*>(&S[16 + j0 - 16]);
        float4 u256 = *reinterpret_cast<const float4*>(&S[16 + j0 + 256]);
        float4 u512 = *reinterpret_cast<const float4*>(&S[16 + j0 + 512]);

        // packed neighbor pairs; (p1,p2) serves both rn01 and ln23
        ull P01  = f2_pack(p[0], p[1]);
        ull P23  = f2_pack(p[2], p[3]);
        ull M12  = f2_pack(p[1], p[2]);
        ull RN23 = f2_pack(p[3], rgt);
        ull LN01 = f2_pack(lft, p[0]);
        ull n16a = f2_pack(u16.x, u16.y),  n16b = f2_pack(u16.z, u16.w);
        ull d16a = f2_pack(d16.x, d16.y),  d16b = f2_pack(d16.z, d16.w);
        ull q2a  = f2_pack(u256.x, u256.y), q2b = f2_pack(u256.z, u256.w);
        ull q4a  = f2_pack(u512.x, u512.y), q4b = f2_pack(u512.z, u512.w);

        // acc pair 0/1
        ull inA = f2_mul(c01[0], P01);
        inA = f2_fma(c01[1], M12, inA);
        inA = f2_fma(c01[2], LN01, inA);
        ull acc01 = f2_mul(csP, inA);
        acc01 = f2_fma(cpP, f2_mul(c01[3], n16a), acc01);
        acc01 = f2_fma(cmP, f2_mul(c01[4], d16a), acc01);
        acc01 = f2_fma(c2P, f2_mul(c01[5], q2a), acc01);
        acc01 = f2_fma(c4P, f2_mul(c01[6], q4a), acc01);
        // acc pair 2/3
        ull inB = f2_mul(c23[0], P23);
        inB = f2_fma(c23[1], RN23, inB);
        inB = f2_fma(c23[2], M12, inB);
        ull acc23 = f2_mul(csP, inB);
        acc23 = f2_fma(cpP, f2_mul(c23[3], n16b), acc23);
        acc23 = f2_fma(cmP, f2_mul(c23[4], d16b), acc23);
        acc23 = f2_fma(c2P, f2_mul(c23[5], q2b), acc23);
        acc23 = f2_fma(c4P, f2_mul(c23[6], q4b), acc23);

        float a0, a1, a2, a3;
        f2_unpack(a0, a1, acc01);
        f2_unpack(a2, a3, acc23);
        v[0] = emv.x + __logf(a0) + m;   // amax folded into em
        v[1] = emv.y + __logf(a1) + m;
        v[2] = emv.z + __logf(a2) + m;
        v[3] = emv.w + __logf(a3) + m;

        // tail: publish next buffers
        float lmn = redux_max_f32(fmaxf(fmaxf(v[0], v[1]), fmaxf(v[2], v[3])));
        lmn = fmaxf(lmn, -3.4e38f);
        #pragma unroll
        for (int st = 0; st < 4; st++) p[st] = __expf(v[st] - lmn);
        *reinterpret_cast<float4*>(&sp[bi ^ 1][16 + j0]) = make_float4(p[0], p[1], p[2], p[3]);
        if (lane == 0) red[bi ^ 1][wid] = lmn;
        rgt = __shfl_down_sync(0xffffffffu, p[0], 1);
        lft = __shfl_up_sync(0xffffffffu, p[3], 1);
        *reinterpret_cast<float4*>(out + ((size_t)l * BNUM + b) * SNUM + j0)
            = make_float4(v[0], v[1], v[2], v[3]);
        // prefetch next step's emissions (clamped; harmless re-read on last step)
        int ln2 = (l + 1 < LNUM) ? l + 1 : LNUM - 1;
        emv = *reinterpret_cast<const float4*>(
            g_allemis + ((size_t)ln2 * BNUM + b) * SNUM + j0);
        lm = lmn;
        __syncthreads();
    }
}

// ---------------- launch ----------------
extern "C" void kernel_launch(void* const* d_in, const int* in_sizes, int n_in,
                              void* d_out, int out_size) {
    const int*   stories = nullptr;
    const float* trans_w = nullptr;
    const float* emis_w  = nullptr;
    const float* prior_w = nullptr;
    for (int i = 0; i < n_in; i++) {
        switch (in_sizes[i]) {
            case BNUM * LNUM * WNUM: stories = (const int*)d_in[i];   break; // 2048
            case SNUM * 7:           trans_w = (const float*)d_in[i]; break; // 28672
            case SNUM * VNUM:        emis_w  = (const float*)d_in[i]; break; // 8388608
            case SNUM:               prior_w = (const float*)d_in[i]; break; // 4096
            default: break; // story_length scalar
        }
    }
    float* out = (float*)d_out;

    k_prep<<<SNUM + 16 + 1, 256>>>(emis_w, trans_w, prior_w);
    k_smooth<<<dim3(VNUM / 32, ZDIM), 256>>>(emis_w);
    k_gather<<<dim3(BNUM, LNUM), 256>>>(stories, prior_w);
    k_forward<<<BNUM, 1024>>>(out);
}